// round 14
// baseline (speedup 1.0000x reference)
#include <cuda_runtime.h>
#include <cuda_bf16.h>
#include <cstdint>

#define NS   8192
#define DIM  128
#define NC   1024
#define MARGIN 0.3f
#define LISTCAP 64
#define KK   256          // 2*DIM bf16 cols: [hi|lo] for both A' and B'

// ---------------- scratch (device globals; ALL zero-init, self-resetting) ----
__device__ __align__(16) unsigned short g_A2[NC * KK];
__device__ __align__(16) unsigned short g_B2[NS * KK];
__device__ float    g_cm2[NC];
__device__ int      g_count[NC];        // scatter cursor == class count
__device__ int      g_list[NC * LISTCAP];
__device__ float    g_x2[NS];
__device__ unsigned g_pos[NC];          // max enc(d2) over positives (init 0)
__device__ unsigned g_negc[NC];         // max ~enc(d2) over negatives (init 0)
__device__ unsigned g_done;

// order-preserving float <-> uint encoding
__device__ __forceinline__ unsigned encf(float f) {
    unsigned u = __float_as_uint(f);
    return (u & 0x80000000u) ? ~u : (u | 0x80000000u);
}
__device__ __forceinline__ float decf(unsigned e) {
    return (e & 0x80000000u) ? __uint_as_float(e ^ 0x80000000u)
                             : __uint_as_float(~e);
}
__device__ __forceinline__ uint32_t smem_u32(const void* p) {
    uint32_t a;
    asm("{ .reg .u64 t; cvta.to.shared.u64 t, %1; cvt.u32.u64 %0, t; }"
        : "=r"(a) : "l"(p));
    return a;
}
__device__ __forceinline__ void ldm_x4(uint32_t& r0, uint32_t& r1,
                                       uint32_t& r2, uint32_t& r3, uint32_t a) {
    asm volatile("ldmatrix.sync.aligned.m8n8.x4.shared.b16 {%0,%1,%2,%3}, [%4];"
                 : "=r"(r0), "=r"(r1), "=r"(r2), "=r"(r3) : "r"(a));
}
__device__ __forceinline__ void mma16816(float* c, const uint32_t* a,
                                         const uint32_t* b) {
    asm volatile("mma.sync.aligned.m16n8k16.row.col.f32.bf16.bf16.f32 "
                 "{%0,%1,%2,%3}, {%4,%5,%6,%7}, {%8,%9}, {%0,%1,%2,%3};"
                 : "+f"(c[0]), "+f"(c[1]), "+f"(c[2]), "+f"(c[3])
                 : "r"(a[0]), "r"(a[1]), "r"(a[2]), "r"(a[3]),
                   "r"(b[0]), "r"(b[1]));
}
__device__ __forceinline__ void cpasync16(uint32_t saddr, const void* gaddr) {
    asm volatile("cp.async.cg.shared.global [%0], [%1], 16;"
                 :: "r"(saddr), "l"(gaddr));
}
#define CP_COMMIT() asm volatile("cp.async.commit_group;" ::: "memory")
#define CP_WAIT0()  asm volatile("cp.async.wait_group 0;" ::: "memory")

// ---------------- K1: row norms + split-convert + atomic scatter lists -------
__global__ __launch_bounds__(1024) void k_pre(const float* __restrict__ X,
                                              const int* __restrict__ T) {
    int tid = threadIdx.x, w = tid >> 5, lane = tid & 31;
    int row = blockIdx.x * 32 + w;
    const float4* rp = reinterpret_cast<const float4*>(X + (size_t)row * DIM);
    float4 v = rp[lane];
    float s = v.x * v.x + v.y * v.y + v.z * v.z + v.w * v.w;
    #pragma unroll
    for (int o = 16; o; o >>= 1) s += __shfl_xor_sync(0xffffffffu, s, o);
    if (lane == 0) {
        g_x2[row] = s;
        int t = T[row];
        int pos = atomicAdd(&g_count[t], 1);        // order fixed by sort later
        if (pos < LISTCAP) g_list[t * LISTCAP + pos] = row;
    }
    __nv_bfloat16 h0 = __float2bfloat16(v.x), h1 = __float2bfloat16(v.y);
    __nv_bfloat16 h2 = __float2bfloat16(v.z), h3 = __float2bfloat16(v.w);
    __nv_bfloat16 l0 = __float2bfloat16(v.x - __bfloat162float(h0));
    __nv_bfloat16 l1 = __float2bfloat16(v.y - __bfloat162float(h1));
    __nv_bfloat16 l2 = __float2bfloat16(v.z - __bfloat162float(h2));
    __nv_bfloat16 l3 = __float2bfloat16(v.w - __bfloat162float(h3));
    ushort4 hv, lv;
    hv.x = __bfloat16_as_ushort(h0); hv.y = __bfloat16_as_ushort(h1);
    hv.z = __bfloat16_as_ushort(h2); hv.w = __bfloat16_as_ushort(h3);
    lv.x = __bfloat16_as_ushort(l0); lv.y = __bfloat16_as_ushort(l1);
    lv.z = __bfloat16_as_ushort(l2); lv.w = __bfloat16_as_ushort(l3);
    unsigned short* B2 = g_B2 + (size_t)row * KK;
    *reinterpret_cast<ushort4*>(B2 + lane * 4)       = hv;  // blk0: hi
    *reinterpret_cast<ushort4*>(B2 + 128 + lane * 4) = lv;  // blk1: lo
}

// ---------------- K2: rank-sort indices + class means + ||m||^2 --------------
__global__ __launch_bounds__(128) void k_centers(const float* __restrict__ X) {
    __shared__ int sidx[LISTCAP], ssort[LISTCAP];
    int c = blockIdx.x, tid = threadIdx.x;
    int cnt = g_count[c];
    int cl = cnt > LISTCAP ? LISTCAP : cnt;
    if (tid < cl) sidx[tid] = g_list[c * LISTCAP + tid];
    __syncthreads();
    if (tid < cl) {                       // rank sort (indices unique)
        int v = sidx[tid], rank = 0;
        for (int j = 0; j < cl; j++) rank += (sidx[j] < v);
        ssort[rank] = v;
    }
    __syncthreads();
    float s = 0.f;
    int i = 0;
    for (; i + 4 <= cl; i += 4) {
        int i0 = ssort[i], i1 = ssort[i+1], i2 = ssort[i+2], i3 = ssort[i+3];
        s += X[(size_t)i0 * DIM + tid];
        s += X[(size_t)i1 * DIM + tid];
        s += X[(size_t)i2 * DIM + tid];
        s += X[(size_t)i3 * DIM + tid];
    }
    for (; i < cl; i++) s += X[(size_t)ssort[i] * DIM + tid];
    float m = (cnt > 0) ? s / (float)cnt : 0.f;
    __nv_bfloat16 hm = __float2bfloat16(m);
    __nv_bfloat16 lm = __float2bfloat16(m - __bfloat162float(hm));
    g_A2[(size_t)c * KK + tid]       = __bfloat16_as_ushort(hm);
    g_A2[(size_t)c * KK + 128 + tid] = __bfloat16_as_ushort(lm);
    float q = m * m;
    #pragma unroll
    for (int o = 16; o; o >>= 1) q += __shfl_xor_sync(0xffffffffu, q, o);
    __shared__ float r[4];
    if ((tid & 31) == 0) r[tid >> 5] = q;
    __syncthreads();
    if (tid == 0) g_cm2[c] = r[0] + r[1] + r[2] + r[3];
}

// ---------------- K3: HMMA GEMM, dedup schedule, 16 warps + mining -----------
// 256 CTAs (8 class-tiles x 32 n-groups, single wave @2 CTA/SM); 512 thr =
// 16 warps (4m x 4n), warp tile 32m x 32n, per-thread micro 2mt x 4nt.
// KK=256 layout [hi|lo]: chunks 0,1 = hi (64 cols each), 2,3 = lo.
// Compute: c0 A0*B0  c1 A0*B2  c2 A2*B0  c3 A1*B1  c4 A1*B3  c5 A3*B1
// Buffers A0,A1,B0,B1 (4 x 18432 B). Prefetch (during c, one tile ahead):
//   c0:B2->B1  c1:A2->A1  c2:A1->A0 + B1->B1  c3:B3->B0  c4:A3->A1
//   c5: next n-tile's A0->A0 + B0->B0
#define SROW 72
#define TILEB 18432
#define SMEM_MMA (TILEB * 4)
#define GRID_MMA 256
__global__ __launch_bounds__(512, 2) void k_mma(const int* __restrict__ T,
                                                float* __restrict__ out,
                                                int out_size) {
    extern __shared__ __align__(16) char dyn[];
    __shared__ float    scm2[128], sx2[128];
    __shared__ int      sTl[128];
    __shared__ unsigned spos[128], snegc[128];
    __shared__ unsigned is_last;

    int tid = threadIdx.x, lane = tid & 31, w = tid >> 5;
    int wm = w & 3, wn = w >> 2;           // warp grid 4m x 4n
    int cbase = (blockIdx.x & 7) * 128;

    if (tid < 128) {
        scm2[tid]  = g_cm2[cbase + tid];
        spos[tid]  = 0u;
        snegc[tid] = 0u;
    }

    uint32_t dynu = smem_u32(dyn);
    const uint4* Ag = reinterpret_cast<const uint4*>(g_A2);  // 32 u4 per row
    const uint4* Bg = reinterpret_cast<const uint4*>(g_B2);

    int ir[2], iq[2];
    #pragma unroll
    for (int k = 0; k < 2; k++) { int i = tid + k * 512; ir[k] = i >> 3; iq[k] = i & 7; }

    int am = wm * 32 + (lane & 15);
    uint32_t offAf = (uint32_t)(am * SROW + (lane >> 4) * 8) * 2;
    int bn = wn * 32 + (lane >> 4) * 8 + (lane & 7);
    uint32_t offBf = (uint32_t)(bn * SROW + ((lane >> 3) & 1) * 8) * 2;

    // schedule tables (indexed by chunk; KK=256 chunk ids)
    const int abufc[6]  = {0, 0, 1, 0, 0, 1};
    const int bbufc[6]  = {0, 1, 0, 1, 0, 1};
    const int fac[6]    = {-1, 2, 1, -1, 3, 0};   // A src chunk to prefetch
    const int fabufc[6] = { 0, 1, 0,  0, 1, 0};
    const int fbc[6]    = { 2, -1, 1, 3, -1, 0};  // B src chunk to prefetch
    const int fbbufc[6] = { 1,  0, 1, 0,  0, 0};

    // prologue: A0->bufA0, B0->bufB0 for tile 0
    {
        int nb0 = (blockIdx.x >> 3) * 128;
        #pragma unroll
        for (int k = 0; k < 2; k++) {
            uint32_t sa = dynu + (uint32_t)(ir[k] * 9 + iq[k]) * 16;
            cpasync16(sa,             Ag + (size_t)(cbase + ir[k]) * 32 + iq[k]);
            cpasync16(sa + 2 * TILEB, Bg + (size_t)(nb0 + ir[k]) * 32 + iq[k]);
        }
        CP_COMMIT();
    }

    #pragma unroll 1
    for (int it = 0; it < 2; it++) {
        int nbase  = (blockIdx.x >> 3) * 128 + it * 4096;
        int nbase2 = (blockIdx.x >> 3) * 128 + 4096;       // tile-1 base
        __syncthreads();                  // prev epilogue done before sx2 reuse
        if (tid < 128) {
            sx2[tid] = g_x2[nbase + tid];
            sTl[tid] = T[nbase + tid];
        }

        float acc[2][4][4];
        #pragma unroll
        for (int mt = 0; mt < 2; mt++)
            #pragma unroll
            for (int nt = 0; nt < 4; nt++)
                #pragma unroll
                for (int k = 0; k < 4; k++) acc[mt][nt][k] = 0.f;

        #pragma unroll
        for (int c = 0; c < 6; c++) {
            CP_WAIT0();
            __syncthreads();              // data visible + prev compute done
            uint32_t curA = dynu + (uint32_t)abufc[c] * TILEB;
            uint32_t curB = dynu + (uint32_t)(2 + bbufc[c]) * TILEB;
            // prefetch for chunk c+1 (or next tile's c0 at c==5)
            int fA = fac[c], fB = fbc[c];
            if (c == 5 && it == 1) { fA = -1; fB = -1; }
            if (fA >= 0) {
                uint32_t dst = dynu + (uint32_t)fabufc[c] * TILEB;
                #pragma unroll
                for (int k = 0; k < 2; k++)
                    cpasync16(dst + (uint32_t)(ir[k] * 9 + iq[k]) * 16,
                              Ag + (size_t)(cbase + ir[k]) * 32 + fA * 8 + iq[k]);
            }
            if (fB >= 0) {
                int nbF = (c == 5) ? nbase2 : nbase;
                uint32_t dst = dynu + (uint32_t)(2 + fbbufc[c]) * TILEB;
                #pragma unroll
                for (int k = 0; k < 2; k++)
                    cpasync16(dst + (uint32_t)(ir[k] * 9 + iq[k]) * 16,
                              Bg + (size_t)(nbF + ir[k]) * 32 + fB * 8 + iq[k]);
            }
            CP_COMMIT();
            // compute chunk c
            #pragma unroll
            for (int kk = 0; kk < 4; kk++) {
                uint32_t b[4][2];
                #pragma unroll
                for (int np = 0; np < 2; np++) {
                    uint32_t addr = curB + offBf + (uint32_t)(np * 16 * SROW + kk * 16) * 2;
                    ldm_x4(b[np*2][0], b[np*2][1], b[np*2+1][0], b[np*2+1][1], addr);
                }
                #pragma unroll
                for (int mt = 0; mt < 2; mt++) {
                    uint32_t a[4];
                    uint32_t addr = curA + offAf + (uint32_t)(mt * 16 * SROW + kk * 16) * 2;
                    ldm_x4(a[0], a[1], a[2], a[3], addr);
                    #pragma unroll
                    for (int nt = 0; nt < 4; nt++)
                        mma16816(acc[mt][nt], a, b[nt]);
                }
            }
        }
        __syncthreads();                  // compute done before next overwrite

        // epilogue: hard mining into smem accumulators
        #pragma unroll
        for (int mt = 0; mt < 2; mt++) {
            #pragma unroll
            for (int h = 0; h < 2; h++) {
                int mloc = wm * 32 + mt * 16 + (lane >> 2) + h * 8;
                int cls  = cbase + mloc;
                float c2 = scm2[mloc];
                unsigned ep = 0u, enc = 0u;
                #pragma unroll
                for (int nt = 0; nt < 4; nt++) {
                    #pragma unroll
                    for (int q = 0; q < 2; q++) {
                        int nloc = wn * 32 + nt * 8 + (lane & 3) * 2 + q;
                        float d2 = c2 + sx2[nloc] - 2.f * acc[mt][nt][h * 2 + q];
                        unsigned e = encf(d2);
                        if (sTl[nloc] == cls) ep  = ep  > e  ? ep  : e;
                        else                  enc = enc > ~e ? enc : ~e;
                    }
                }
                #pragma unroll
                for (int o = 1; o <= 2; o <<= 1) {
                    unsigned tp = __shfl_xor_sync(0xffffffffu, ep, o);
                    unsigned tn = __shfl_xor_sync(0xffffffffu, enc, o);
                    ep  = ep  > tp ? ep  : tp;
                    enc = enc > tn ? enc : tn;
                }
                if ((lane & 3) == 0) {
                    atomicMax(&spos[mloc], ep);
                    atomicMax(&snegc[mloc], enc);
                }
            }
        }
    }
    __syncthreads();
    if (tid < 128) {
        atomicMax(&g_pos[cbase + tid],  spos[tid]);
        atomicMax(&g_negc[cbase + tid], snegc[tid]);
    }

    // ---- fused final reduction + global self-reset (last CTA) ----
    __threadfence();
    __syncthreads();
    if (tid == 0)
        is_last = (atomicAdd(&g_done, 1u) == (unsigned)(GRID_MMA - 1)) ? 1u : 0u;
    __syncthreads();
    if (is_last) {
        float l = 0.f, p = 0.f;
        for (int c = tid; c < NC; c += 512) {
            int cnt = g_count[c];
            if (cnt > 0) {
                float pos = decf(g_pos[c]);
                float neg = decf(~g_negc[c]);
                float d = pos - neg + MARGIN;
                l += (float)cnt * (d > 0.f ? d : 0.f);
                p += (float)cnt * (neg > pos ? 1.f : 0.f);
            }
        }
        #pragma unroll
        for (int o = 16; o; o >>= 1) {
            l += __shfl_xor_sync(0xffffffffu, l, o);
            p += __shfl_xor_sync(0xffffffffu, p, o);
        }
        __shared__ float rl[16], rp[16];
        if ((tid & 31) == 0) { rl[tid >> 5] = l; rp[tid >> 5] = p; }
        __syncthreads();
        if (tid == 0) {
            float L = 0.f, P = 0.f;
            #pragma unroll
            for (int i = 0; i < 16; i++) { L += rl[i]; P += rp[i]; }
            out[0] = L / (float)NS;
            if (out_size > 1) out[1] = P / (float)NS;
            g_done = 0u;
        }
        __syncthreads();                 // all reads of g_count done
        for (int c = tid; c < NC; c += 512) {
            g_count[c] = 0;
            g_pos[c]   = 0u;
            g_negc[c]  = 0u;
        }
    }
}

// ---------------- launch -----------------------------------------------------
extern "C" void kernel_launch(void* const* d_in, const int* in_sizes, int n_in,
                              void* d_out, int out_size) {
    const float* X = (const float*)d_in[0];
    const int*   T = (const int*)d_in[1];
    float*       O = (float*)d_out;

    cudaFuncSetAttribute(k_mma, cudaFuncAttributeMaxDynamicSharedMemorySize,
                         SMEM_MMA);

    k_pre<<<NS / 32, 1024>>>(X, T);
    k_centers<<<NC, 128>>>(X);
    k_mma<<<GRID_MMA, 512, SMEM_MMA>>>(T, O, out_size);
}

// round 15
// speedup vs baseline: 1.4844x; 1.4844x over previous
#include <cuda_runtime.h>
#include <cuda_bf16.h>
#include <cstdint>

#define NS   8192
#define DIM  128
#define NC   1024
#define MARGIN 0.3f
#define LISTCAP 64
#define KK   384          // 3*DIM bf16 cols: A'=[hi|-|lo], B'=[hi|lo|-]
                          // (middle/last dup-hi blocks are DEAD: never read)

// ---------------- scratch (device globals; ALL zero-init, self-resetting) ----
__device__ __align__(16) unsigned short g_A2[NC * KK];
__device__ __align__(16) unsigned short g_B2[NS * KK];
__device__ float    g_cm2[NC];
__device__ int      g_count[NC];        // scatter cursor == class count
__device__ int      g_list[NC * LISTCAP];
__device__ float    g_x2[NS];
__device__ unsigned g_pos[NC];          // max enc(d2) over positives (init 0)
__device__ unsigned g_negc[NC];         // max ~enc(d2) over negatives (init 0)
__device__ unsigned g_done;

// order-preserving float <-> uint encoding
__device__ __forceinline__ unsigned encf(float f) {
    unsigned u = __float_as_uint(f);
    return (u & 0x80000000u) ? ~u : (u | 0x80000000u);
}
__device__ __forceinline__ float decf(unsigned e) {
    return (e & 0x80000000u) ? __uint_as_float(e ^ 0x80000000u)
                             : __uint_as_float(~e);
}
__device__ __forceinline__ uint32_t smem_u32(const void* p) {
    uint32_t a;
    asm("{ .reg .u64 t; cvta.to.shared.u64 t, %1; cvt.u32.u64 %0, t; }"
        : "=r"(a) : "l"(p));
    return a;
}
__device__ __forceinline__ void ldm_x4(uint32_t& r0, uint32_t& r1,
                                       uint32_t& r2, uint32_t& r3, uint32_t a) {
    asm volatile("ldmatrix.sync.aligned.m8n8.x4.shared.b16 {%0,%1,%2,%3}, [%4];"
                 : "=r"(r0), "=r"(r1), "=r"(r2), "=r"(r3) : "r"(a));
}
__device__ __forceinline__ void mma16816(float* c, const uint32_t* a,
                                         const uint32_t* b) {
    asm volatile("mma.sync.aligned.m16n8k16.row.col.f32.bf16.bf16.f32 "
                 "{%0,%1,%2,%3}, {%4,%5,%6,%7}, {%8,%9}, {%0,%1,%2,%3};"
                 : "+f"(c[0]), "+f"(c[1]), "+f"(c[2]), "+f"(c[3])
                 : "r"(a[0]), "r"(a[1]), "r"(a[2]), "r"(a[3]),
                   "r"(b[0]), "r"(b[1]));
}
__device__ __forceinline__ void cpasync16(uint32_t saddr, const void* gaddr) {
    asm volatile("cp.async.cg.shared.global [%0], [%1], 16;"
                 :: "r"(saddr), "l"(gaddr));
}
#define CP_COMMIT() asm volatile("cp.async.commit_group;" ::: "memory")
#define CP_WAIT0()  asm volatile("cp.async.wait_group 0;" ::: "memory")

// ---------------- K1: row norms + split-convert + atomic scatter lists -------
__global__ __launch_bounds__(1024) void k_pre(const float* __restrict__ X,
                                              const int* __restrict__ T) {
    int tid = threadIdx.x, w = tid >> 5, lane = tid & 31;
    int row = blockIdx.x * 32 + w;
    const float4* rp = reinterpret_cast<const float4*>(X + (size_t)row * DIM);
    float4 v = rp[lane];
    float s = v.x * v.x + v.y * v.y + v.z * v.z + v.w * v.w;
    #pragma unroll
    for (int o = 16; o; o >>= 1) s += __shfl_xor_sync(0xffffffffu, s, o);
    if (lane == 0) {
        g_x2[row] = s;
        int t = T[row];
        int pos = atomicAdd(&g_count[t], 1);        // order fixed by sort later
        if (pos < LISTCAP) g_list[t * LISTCAP + pos] = row;
    }
    __nv_bfloat16 h0 = __float2bfloat16(v.x), h1 = __float2bfloat16(v.y);
    __nv_bfloat16 h2 = __float2bfloat16(v.z), h3 = __float2bfloat16(v.w);
    __nv_bfloat16 l0 = __float2bfloat16(v.x - __bfloat162float(h0));
    __nv_bfloat16 l1 = __float2bfloat16(v.y - __bfloat162float(h1));
    __nv_bfloat16 l2 = __float2bfloat16(v.z - __bfloat162float(h2));
    __nv_bfloat16 l3 = __float2bfloat16(v.w - __bfloat162float(h3));
    ushort4 hv, lv;
    hv.x = __bfloat16_as_ushort(h0); hv.y = __bfloat16_as_ushort(h1);
    hv.z = __bfloat16_as_ushort(h2); hv.w = __bfloat16_as_ushort(h3);
    lv.x = __bfloat16_as_ushort(l0); lv.y = __bfloat16_as_ushort(l1);
    lv.z = __bfloat16_as_ushort(l2); lv.w = __bfloat16_as_ushort(l3);
    unsigned short* B2 = g_B2 + (size_t)row * KK;
    *reinterpret_cast<ushort4*>(B2 + lane * 4)       = hv;  // blk0: hi (read)
    *reinterpret_cast<ushort4*>(B2 + 128 + lane * 4) = lv;  // blk1: lo (read)
    // blk2 (cols 256-383) is never read by k_mma — store elided
}

// ---------------- K2: rank-sort indices + class means + ||m||^2 --------------
__global__ __launch_bounds__(128) void k_centers(const float* __restrict__ X) {
    __shared__ int sidx[LISTCAP], ssort[LISTCAP];
    int c = blockIdx.x, tid = threadIdx.x;
    int cnt = g_count[c];
    int cl = cnt > LISTCAP ? LISTCAP : cnt;
    if (tid < cl) sidx[tid] = g_list[c * LISTCAP + tid];
    __syncthreads();
    if (tid < cl) {                       // rank sort (indices unique)
        int v = sidx[tid], rank = 0;
        for (int j = 0; j < cl; j++) rank += (sidx[j] < v);
        ssort[rank] = v;
    }
    __syncthreads();
    float s = 0.f;
    int i = 0;
    for (; i + 4 <= cl; i += 4) {
        int i0 = ssort[i], i1 = ssort[i+1], i2 = ssort[i+2], i3 = ssort[i+3];
        s += X[(size_t)i0 * DIM + tid];
        s += X[(size_t)i1 * DIM + tid];
        s += X[(size_t)i2 * DIM + tid];
        s += X[(size_t)i3 * DIM + tid];
    }
    for (; i < cl; i++) s += X[(size_t)ssort[i] * DIM + tid];
    float m = (cnt > 0) ? s / (float)cnt : 0.f;
    __nv_bfloat16 hm = __float2bfloat16(m);
    __nv_bfloat16 lm = __float2bfloat16(m - __bfloat162float(hm));
    g_A2[(size_t)c * KK + tid]       = __bfloat16_as_ushort(hm);  // blk0: hi
    // blk1 (cols 128-255) never read — store elided
    g_A2[(size_t)c * KK + 256 + tid] = __bfloat16_as_ushort(lm);  // blk2: lo
    float q = m * m;
    #pragma unroll
    for (int o = 16; o; o >>= 1) q += __shfl_xor_sync(0xffffffffu, q, o);
    __shared__ float r[4];
    if ((tid & 31) == 0) r[tid >> 5] = q;
    __syncthreads();
    if (tid == 0) g_cm2[c] = r[0] + r[1] + r[2] + r[3];
}

// ---------------- K3: HMMA GEMM, dedup schedule, 16 warps + mining -----------
// 256 CTAs (8 class-tiles x 32 n-groups, single wave @2 CTA/SM); 512 thr =
// 16 warps (4m x 4n), warp tile 32m x 32n, per-thread micro 2mt x 4nt.
// 768 B global row stride (48 u4) — NON-power-of-two, spreads L2 slices.
// A chunks used: 0,1 (hi), 4,5 (lo). B chunks used: 0,1 (hi), 2,3 (lo).
// Compute: c0 Ah0*Bh0 c1 Ah0*Bl0 c2 Al0*Bh0 c3 Ah1*Bh1 c4 Ah1*Bl1 c5 Al1*Bh1
#define SROW 72
#define TILEB 18432
#define SMEM_MMA (TILEB * 4)
#define GRID_MMA 256
__global__ __launch_bounds__(512, 2) void k_mma(const int* __restrict__ T,
                                                float* __restrict__ out,
                                                int out_size) {
    extern __shared__ __align__(16) char dyn[];
    __shared__ float    scm2[128], sx2[128];
    __shared__ int      sTl[128];
    __shared__ unsigned spos[128], snegc[128];
    __shared__ unsigned is_last;

    int tid = threadIdx.x, lane = tid & 31, w = tid >> 5;
    int wm = w & 3, wn = w >> 2;           // warp grid 4m x 4n
    int cbase = (blockIdx.x & 7) * 128;

    if (tid < 128) {
        scm2[tid]  = g_cm2[cbase + tid];
        spos[tid]  = 0u;
        snegc[tid] = 0u;
    }

    uint32_t dynu = smem_u32(dyn);
    const uint4* Ag = reinterpret_cast<const uint4*>(g_A2);
    const uint4* Bg = reinterpret_cast<const uint4*>(g_B2);

    int ir[2], iq[2];
    #pragma unroll
    for (int k = 0; k < 2; k++) { int i = tid + k * 512; ir[k] = i >> 3; iq[k] = i & 7; }

    int am = wm * 32 + (lane & 15);
    uint32_t offAf = (uint32_t)(am * SROW + (lane >> 4) * 8) * 2;
    int bn = wn * 32 + (lane >> 4) * 8 + (lane & 7);
    uint32_t offBf = (uint32_t)(bn * SROW + ((lane >> 3) & 1) * 8) * 2;

    // schedule tables (indexed by chunk; KK=384 chunk ids)
    const int abufc[6]  = {0, 0, 1, 0, 0, 1};
    const int bbufc[6]  = {0, 1, 0, 1, 0, 1};
    const int fac[6]    = {-1, 4, 1, -1, 5, 0};   // A src chunk to prefetch
    const int fabufc[6] = { 0, 1, 0,  0, 1, 0};
    const int fbc[6]    = { 2, -1, 1, 3, -1, 0};  // B src chunk to prefetch
    const int fbbufc[6] = { 1,  0, 1, 0,  0, 0};

    // prologue: Ah0->A0, Bh0->B0 for tile 0
    {
        int nb0 = (blockIdx.x >> 3) * 128;
        #pragma unroll
        for (int k = 0; k < 2; k++) {
            uint32_t sa = dynu + (uint32_t)(ir[k] * 9 + iq[k]) * 16;
            cpasync16(sa,             Ag + (size_t)(cbase + ir[k]) * 48 + iq[k]);
            cpasync16(sa + 2 * TILEB, Bg + (size_t)(nb0 + ir[k]) * 48 + iq[k]);
        }
        CP_COMMIT();
    }

    #pragma unroll 1
    for (int it = 0; it < 2; it++) {
        int nbase  = (blockIdx.x >> 3) * 128 + it * 4096;
        int nbase2 = (blockIdx.x >> 3) * 128 + 4096;       // tile-1 base
        __syncthreads();                  // prev epilogue done before sx2 reuse
        if (tid < 128) {
            sx2[tid] = g_x2[nbase + tid];
            sTl[tid] = T[nbase + tid];
        }

        float acc[2][4][4];
        #pragma unroll
        for (int mt = 0; mt < 2; mt++)
            #pragma unroll
            for (int nt = 0; nt < 4; nt++)
                #pragma unroll
                for (int k = 0; k < 4; k++) acc[mt][nt][k] = 0.f;

        #pragma unroll
        for (int c = 0; c < 6; c++) {
            CP_WAIT0();
            __syncthreads();              // data visible + prev compute done
            uint32_t curA = dynu + (uint32_t)abufc[c] * TILEB;
            uint32_t curB = dynu + (uint32_t)(2 + bbufc[c]) * TILEB;
            // prefetch for chunk c+1 (or next tile's c0 at c==5)
            int fA = fac[c], fB = fbc[c];
            if (c == 5 && it == 1) { fA = -1; fB = -1; }
            if (fA >= 0) {
                uint32_t dst = dynu + (uint32_t)fabufc[c] * TILEB;
                #pragma unroll
                for (int k = 0; k < 2; k++)
                    cpasync16(dst + (uint32_t)(ir[k] * 9 + iq[k]) * 16,
                              Ag + (size_t)(cbase + ir[k]) * 48 + fA * 8 + iq[k]);
            }
            if (fB >= 0) {
                int nbF = (c == 5) ? nbase2 : nbase;
                uint32_t dst = dynu + (uint32_t)(2 + fbbufc[c]) * TILEB;
                #pragma unroll
                for (int k = 0; k < 2; k++)
                    cpasync16(dst + (uint32_t)(ir[k] * 9 + iq[k]) * 16,
                              Bg + (size_t)(nbF + ir[k]) * 48 + fB * 8 + iq[k]);
            }
            CP_COMMIT();
            // compute chunk c
            #pragma unroll
            for (int kk = 0; kk < 4; kk++) {
                uint32_t b[4][2];
                #pragma unroll
                for (int np = 0; np < 2; np++) {
                    uint32_t addr = curB + offBf + (uint32_t)(np * 16 * SROW + kk * 16) * 2;
                    ldm_x4(b[np*2][0], b[np*2][1], b[np*2+1][0], b[np*2+1][1], addr);
                }
                #pragma unroll
                for (int mt = 0; mt < 2; mt++) {
                    uint32_t a[4];
                    uint32_t addr = curA + offAf + (uint32_t)(mt * 16 * SROW + kk * 16) * 2;
                    ldm_x4(a[0], a[1], a[2], a[3], addr);
                    #pragma unroll
                    for (int nt = 0; nt < 4; nt++)
                        mma16816(acc[mt][nt], a, b[nt]);
                }
            }
        }
        __syncthreads();                  // compute done before next overwrite

        // epilogue: hard mining into smem accumulators
        #pragma unroll
        for (int mt = 0; mt < 2; mt++) {
            #pragma unroll
            for (int h = 0; h < 2; h++) {
                int mloc = wm * 32 + mt * 16 + (lane >> 2) + h * 8;
                int cls  = cbase + mloc;
                float c2 = scm2[mloc];
                unsigned ep = 0u, enc = 0u;
                #pragma unroll
                for (int nt = 0; nt < 4; nt++) {
                    #pragma unroll
                    for (int q = 0; q < 2; q++) {
                        int nloc = wn * 32 + nt * 8 + (lane & 3) * 2 + q;
                        float d2 = c2 + sx2[nloc] - 2.f * acc[mt][nt][h * 2 + q];
                        unsigned e = encf(d2);
                        if (sTl[nloc] == cls) ep  = ep  > e  ? ep  : e;
                        else                  enc = enc > ~e ? enc : ~e;
                    }
                }
                #pragma unroll
                for (int o = 1; o <= 2; o <<= 1) {
                    unsigned tp = __shfl_xor_sync(0xffffffffu, ep, o);
                    unsigned tn = __shfl_xor_sync(0xffffffffu, enc, o);
                    ep  = ep  > tp ? ep  : tp;
                    enc = enc > tn ? enc : tn;
                }
                if ((lane & 3) == 0) {
                    atomicMax(&spos[mloc], ep);
                    atomicMax(&snegc[mloc], enc);
                }
            }
        }
    }
    __syncthreads();
    if (tid < 128) {
        atomicMax(&g_pos[cbase + tid],  spos[tid]);
        atomicMax(&g_negc[cbase + tid], snegc[tid]);
    }

    // ---- fused final reduction + global self-reset (last CTA) ----
    __threadfence();
    __syncthreads();
    if (tid == 0)
        is_last = (atomicAdd(&g_done, 1u) == (unsigned)(GRID_MMA - 1)) ? 1u : 0u;
    __syncthreads();
    if (is_last) {
        float l = 0.f, p = 0.f;
        for (int c = tid; c < NC; c += 512) {
            int cnt = g_count[c];
            if (cnt > 0) {
                float pos = decf(g_pos[c]);
                float neg = decf(~g_negc[c]);
                float d = pos - neg + MARGIN;
                l += (float)cnt * (d > 0.f ? d : 0.f);
                p += (float)cnt * (neg > pos ? 1.f : 0.f);
            }
        }
        #pragma unroll
        for (int o = 16; o; o >>= 1) {
            l += __shfl_xor_sync(0xffffffffu, l, o);
            p += __shfl_xor_sync(0xffffffffu, p, o);
        }
        __shared__ float rl[16], rp[16];
        if ((tid & 31) == 0) { rl[tid >> 5] = l; rp[tid >> 5] = p; }
        __syncthreads();
        if (tid == 0) {
            float L = 0.f, P = 0.f;
            #pragma unroll
            for (int i = 0; i < 16; i++) { L += rl[i]; P += rp[i]; }
            out[0] = L / (float)NS;
            if (out_size > 1) out[1] = P / (float)NS;
            g_done = 0u;
        }
        __syncthreads();                 // all reads of g_count done
        for (int c = tid; c < NC; c += 512) {
            g_count[c] = 0;
            g_pos[c]   = 0u;
            g_negc[c]  = 0u;
        }
    }
}

// ---------------- launch -----------------------------------------------------
extern "C" void kernel_launch(void* const* d_in, const int* in_sizes, int n_in,
                              void* d_out, int out_size) {
    const float* X = (const float*)d_in[0];
    const int*   T = (const int*)d_in[1];
    float*       O = (float*)d_out;

    cudaFuncSetAttribute(k_mma, cudaFuncAttributeMaxDynamicSharedMemorySize,
                         SMEM_MMA);

    k_pre<<<NS / 32, 1024>>>(X, T);
    k_centers<<<NC, 128>>>(X);
    k_mma<<<GRID_MMA, 512, SMEM_MMA>>>(T, O, out_size);
}